// round 12
// baseline (speedup 1.0000x reference)
#include <cuda_runtime.h>
#include <cstdint>

#define NN 512
#define LUT_N 83521            // 17^4
#define NPIX (4 * NN * NN)

// ---------------- device scratch ----------------
__device__ int8_t g_q0[3 * LUT_N];        // stage-0 quantized LUT (int8)
__device__ uint4  g_q1[3 * LUT_N];        // stage-1 quantized LUT (16 ch, biased u8, 16B/row)
__device__ float  g_x1[NPIX];             // stage-0 output image (integers 0..255)

// prefolded sampler weights (see setup_weights)
__device__ unsigned long long g_w0pk[108]; // stage0: (255w/16, 255w/16)
__device__ unsigned long long g_w1pk[108]; // stage1: (w/16 [cur], 255w/16 [prev])
__device__ unsigned long long g_b0pk[12];  // (b/16, b/16)
__device__ unsigned long long g_b1pk[12];
__device__ float              g_rw1[12];   // clamped residual weights

// ---------------- f32x2 helpers ----------------
__device__ __forceinline__ unsigned long long pack2(unsigned lo, unsigned hi) {
    unsigned long long d;
    asm("mov.b64 %0, {%1, %2};" : "=l"(d) : "r"(lo), "r"(hi));
    return d;
}
__device__ __forceinline__ unsigned long long pack2f(float lo, float hi) {
    return pack2(__float_as_uint(lo), __float_as_uint(hi));
}
__device__ __forceinline__ void unpack2(unsigned long long v, float& lo, float& hi) {
    asm("mov.b64 {%0, %1}, %2;" : "=f"(lo), "=f"(hi) : "l"(v));
}
__device__ __forceinline__ unsigned long long fadd2(unsigned long long a, unsigned long long b) {
    unsigned long long d;
    asm("add.rn.f32x2 %0, %1, %2;" : "=l"(d) : "l"(a), "l"(b));
    return d;
}
__device__ __forceinline__ unsigned long long ffma2(unsigned long long a, unsigned long long b,
                                                    unsigned long long c) {
    unsigned long long d;
    asm("fma.rn.f32x2 %0, %1, %2, %3;" : "=l"(d) : "l"(a), "l"(b), "l"(c));
    return d;
}

// ---------------- setup: prefold scales into weights ----------------
__global__ void setup_weights(const float* __restrict__ s0, const float* __restrict__ s1,
                              const float* __restrict__ b0, const float* __restrict__ b1,
                              const float* __restrict__ rw) {
    int i = threadIdx.x;
    if (i < 108) {
        float w0 = s0[i] * (255.0f / 16.0f);
        g_w0pk[i] = pack2f(w0, w0);
        g_w1pk[i] = pack2f(s1[i] * (1.0f / 16.0f), s1[i] * (255.0f / 16.0f));
    }
    if (i < 12) {
        float bb0 = b0[i] * (1.0f / 16.0f);
        g_b0pk[i] = pack2f(bb0, bb0);
        float bb1 = b1[i] * (1.0f / 16.0f);
        g_b1pk[i] = pack2f(bb1, bb1);
        g_rw1[i] = fminf(fmaxf(rw[i], 0.0f), 1.0f);
    }
}

// ---------------- LUT quantization ----------------
__global__ void quant_lut0(const float* __restrict__ src) {
    int i = blockIdx.x * blockDim.x + threadIdx.x;
    if (i < 3 * LUT_N) {
        float q = rintf(src[i] * 127.0f);
        q = fminf(fmaxf(q, -127.0f), 127.0f);
        g_q0[i] = (int8_t)(int)q;
    }
}

__device__ __forceinline__ unsigned q1_byte(float v) {
    float q = rintf(v * 127.0f);
    q = fminf(fmaxf(q, -127.0f), 127.0f);
    return (unsigned)((int)q + 128);   // biased u8
}

// word-per-thread: coalesced float4 reads, coalesced u32 writes
__global__ void quant_lut1(const float* __restrict__ src) {
    int i = blockIdx.x * blockDim.x + threadIdx.x;
    if (i < 3 * LUT_N * 4) {
        float4 f = reinterpret_cast<const float4*>(src)[i];
        unsigned acc = q1_byte(f.x) | (q1_byte(f.y) << 8)
                     | (q1_byte(f.z) << 16) | (q1_byte(f.w) << 24);
        reinterpret_cast<unsigned*>(g_q1)[i] = acc;
    }
}

// ---------------- helpers ----------------
// Rotation-r tap position in the 5x5 neighborhood.
// r=0: X[p+u,q+v]; r=1: X[p+v,q-u]; r=2: X[p-u,q-v]; r=3: X[p-v,q+u]
__device__ __forceinline__ constexpr int nb_idx(int R, int u, int w) {
    int dy = (R == 0) ? u : (R == 1) ? w : (R == 2) ? -u : -w;
    int dx = (R == 0) ? w : (R == 1) ? -u : (R == 2) ? -w : u;
    return (2 + dy) * 5 + (2 + dx);
}

#define CSW(fa_, fb_, ta_, tb_)                         \
    { if (fa_ < fb_) { float tf = fa_; fa_ = fb_; fb_ = tf; \
                       int ti = ta_; ta_ = tb_; tb_ = ti; } }

// 4D simplex on PRE-SCALED inputs v' = v/16 in [0,17).
// la = floor(v'), g = frac(v'); ws already normalized (sum to 1).
__device__ __forceinline__ void simplex(const float v[4], int verts[5], float ws[5]) {
    int la = (int)v[0], lb = (int)v[1], lc = (int)v[2], ld = (int)v[3];
    float f0 = v[0] - (float)la, f1 = v[1] - (float)lb;
    float f2 = v[2] - (float)lc, f3 = v[3] - (float)ld;
    int base = ((la * 17 + lb) * 17 + lc) * 17 + ld;
    int t0 = 4913, t1 = 289, t2 = 17, t3 = 1;
    CSW(f0, f1, t0, t1); CSW(f2, f3, t2, t3);
    CSW(f0, f2, t0, t2); CSW(f1, f3, t1, t3);
    CSW(f1, f2, t1, t2);
    ws[0] = 1.0f - f0;
    ws[1] = f0 - f1;
    ws[2] = f1 - f2;
    ws[3] = f2 - f3;
    ws[4] = f3;
    verts[0] = base;
    verts[1] = verts[0] + t0;
    verts[2] = verts[1] + t1;
    verts[3] = verts[2] + t2;
    verts[4] = verts[3] + t3;
}

// ---------------- stage 0 ----------------
__global__ void __launch_bounds__(256, 3) stage0_kernel(const float* __restrict__ x) {
    int q = blockIdx.x * 32 + threadIdx.x;
    int p = blockIdx.y * 8 + threadIdx.y;
    int b = blockIdx.z;

    unsigned long long pkA[9], pkB[9];   // (R0,R2) and (R1,R3) packed taps (raw pixels)
    {
        const float* img = x + (size_t)b * NN * NN;
        float nb[25];
        int rr[5], cc[5];
#pragma unroll
        for (int i = 0; i < 5; i++) {
            rr[i] = min(max(p - 2 + i, 0), NN - 1);
            cc[i] = min(max(q - 2 + i, 0), NN - 1);
        }
#pragma unroll
        for (int i = 0; i < 5; i++)
#pragma unroll
            for (int j = 0; j < 5; j++)
                nb[i * 5 + j] = __ldg(img + rr[i] * NN + cc[j]);
#pragma unroll
        for (int u = 0; u < 3; u++)
#pragma unroll
            for (int w = 0; w < 3; w++) {
                int iA = nb_idx(0, u, w);
                int iB = nb_idx(1, u, w);
                pkA[u * 3 + w] = pack2f(nb[iA], nb[24 - iA]);
                pkB[u * 3 + w] = pack2f(nb[iB], nb[24 - iB]);
            }
    }

    float total = 0.0f;
#pragma unroll
    for (int s = 0; s < 3; s++) {
        const int8_t* lt = g_q0 + s * LUT_N;

        float v[4][4];
#pragma unroll
        for (int ch = 0; ch < 4; ch++) {
            unsigned long long accA = __ldg(&g_b0pk[s * 4 + ch]);
            unsigned long long accB = accA;
#pragma unroll
            for (int t = 0; t < 9; t++) {
                unsigned long long w2 = __ldg(&g_w0pk[s * 36 + ch * 9 + t]);
                accA = ffma2(w2, pkA[t], accA);
                accB = ffma2(w2, pkB[t], accB);
            }
            unpack2(accA, v[0][ch], v[2][ch]);
            unpack2(accB, v[1][ch], v[3][ch]);
        }

        float acc = 0.0f;
#pragma unroll
        for (int R = 0; R < 4; R++) {
            int verts[5]; float ws[5];
            simplex(v[R], verts, ws);
            float dot = 0.0f;
#pragma unroll
            for (int t = 0; t < 5; t++) dot += ws[t] * (float)__ldg(lt + verts[t]);
            acc = rintf(acc + dot);
        }
        total += acc;
    }
    float o = rintf(fminf(fmaxf(total * (1.0f / 12.0f) + 127.0f, 0.0f), 255.0f));
    g_x1[(size_t)b * NN * NN + p * NN + q] = o;
}

// ---------------- stage 1 ----------------
// fused per-rotation: simplex + gather + accumulate; blk[k] += rintf(c[k]) (exact,
// order-free: every term is integer-valued after rintf)
template <int R>
__device__ __forceinline__ void proc_rot1(const float v[4], const uint4* __restrict__ lt,
                                          float blk[16]) {
    int vt[5]; float ws[5];
    simplex(v, vt, ws);

    uint4 d[5];
#pragma unroll
    for (int t = 0; t < 5; t++) d[t] = __ldg(lt + vt[t]);

    unsigned long long c2[8];
#pragma unroll
    for (int pidx = 0; pidx < 8; pidx++) c2[pidx] = 0ull;
    const unsigned long long B2 = pack2(0xCB000080u, 0xCB000080u);  // (-8388736,-8388736)

#pragma unroll
    for (int t = 0; t < 5; t++) {
        unsigned wtb = __float_as_uint(ws[t]);
        unsigned long long wt2 = pack2(wtb, wtb);
#pragma unroll
        for (int pidx = 0; pidx < 8; pidx++) {
            unsigned word = (pidx < 2) ? d[t].x : (pidx < 4) ? d[t].y
                          : (pidx < 6) ? d[t].z : d[t].w;
            int kk = (pidx & 1) * 2;
            unsigned lo = __byte_perm(word, 0x4B000000u, 0x7540u + kk);
            unsigned hi = __byte_perm(word, 0x4B000000u, 0x7541u + kk);
            unsigned long long m2 = fadd2(pack2(lo, hi), B2);  // exact (byte-128)
            c2[pidx] = ffma2(m2, wt2, c2[pidx]);
        }
    }

    float c[16];
#pragma unroll
    for (int pidx = 0; pidx < 8; pidx++) unpack2(c2[pidx], c[2 * pidx], c[2 * pidx + 1]);

#pragma unroll
    for (int i = 0; i < 4; i++)
#pragma unroll
        for (int j = 0; j < 4; j++) {
            int k = (R == 0) ? (i * 4 + j)
                  : (R == 1) ? ((3 - j) * 4 + i)
                  : (R == 2) ? ((3 - i) * 4 + (3 - j))
                             : (j * 4 + (3 - i));
            blk[i * 4 + j] += rintf(c[k]);
        }
}

__global__ void __launch_bounds__(256, 2) stage1_kernel(const float* __restrict__ x,
                                                        float* __restrict__ out) {
    int q = blockIdx.x * 32 + threadIdx.x;
    int p = blockIdx.y * 8 + threadIdx.y;
    int b = blockIdx.z;

    // packed neighborhood: lane0 = current image (g_x1), lane1 = prev image (raw x)
    unsigned long long pnb[25];
    {
        const float* img1 = g_x1 + (size_t)b * NN * NN;
        const float* img0 = x + (size_t)b * NN * NN;
        int rr[5], cc[5];
#pragma unroll
        for (int i = 0; i < 5; i++) {
            rr[i] = min(max(p - 2 + i, 0), NN - 1);
            cc[i] = min(max(q - 2 + i, 0), NN - 1);
        }
#pragma unroll
        for (int i = 0; i < 5; i++)
#pragma unroll
            for (int j = 0; j < 5; j++) {
                int off = rr[i] * NN + cc[j];
                pnb[i * 5 + j] = pack2f(__ldg(img1 + off), __ldg(img0 + off));
            }
    }

    float blk[16];
#pragma unroll
    for (int k = 0; k < 16; k++) blk[k] = 0.0f;

#pragma unroll
    for (int s = 0; s < 3; s++) {
        const uint4* lt = g_q1 + s * LUT_N;

        // ---- paired conv with prefolded weights: (w/16 | 255w/16) ----
        float v[4][4];   // [R][ch], blended, already in cell units (v/16)
#pragma unroll
        for (int ch = 0; ch < 4; ch++) {
            unsigned long long W2[9];
#pragma unroll
            for (int t = 0; t < 9; t++)
                W2[t] = __ldg(&g_w1pk[s * 36 + ch * 9 + t]);
            unsigned long long B2b = __ldg(&g_b1pk[s * 4 + ch]);
            float rwc = __ldg(&g_rw1[s * 4 + ch]);
#pragma unroll
            for (int R = 0; R < 4; R++) {
                unsigned long long a2 = B2b;
#pragma unroll
                for (int u = 0; u < 3; u++)
#pragma unroll
                    for (int w = 0; w < 3; w++)
                        a2 = ffma2(W2[u * 3 + w], pnb[nb_idx(R, u, w)], a2);
                float vc, vp;
                unpack2(a2, vc, vp);
                v[R][ch] = vc + rwc * (vp - vc);
            }
        }

        proc_rot1<0>(v[0], lt, blk);
        proc_rot1<1>(v[1], lt, blk);
        proc_rot1<2>(v[2], lt, blk);
        proc_rot1<3>(v[3], lt, blk);
    }

    float* op = out + ((size_t)b << 22) + (size_t)(4 * p) * 2048 + 4 * q;
#pragma unroll
    for (int i = 0; i < 4; i++) {
        float4 o;
        o.x = rintf(fminf(fmaxf(blk[i * 4 + 0] * (1.0f / 3.0f), 0.0f), 255.0f)) * (1.0f / 255.0f);
        o.y = rintf(fminf(fmaxf(blk[i * 4 + 1] * (1.0f / 3.0f), 0.0f), 255.0f)) * (1.0f / 255.0f);
        o.z = rintf(fminf(fmaxf(blk[i * 4 + 2] * (1.0f / 3.0f), 0.0f), 255.0f)) * (1.0f / 255.0f);
        o.w = rintf(fminf(fmaxf(blk[i * 4 + 3] * (1.0f / 3.0f), 0.0f), 255.0f)) * (1.0f / 255.0f);
        *reinterpret_cast<float4*>(op + (size_t)i * 2048) = o;
    }
}

// ---------------- launch ----------------
extern "C" void kernel_launch(void* const* d_in, const int* in_sizes, int n_in,
                              void* d_out, int out_size) {
    const float* x     = (const float*)d_in[0];
    const float* lut0  = (const float*)d_in[1];
    const float* lut1  = (const float*)d_in[2];
    const float* samp0 = (const float*)d_in[3];
    const float* samp1 = (const float*)d_in[4];
    const float* sb0   = (const float*)d_in[5];
    const float* sb1   = (const float*)d_in[6];
    const float* resw  = (const float*)d_in[7];

    setup_weights<<<1, 128>>>(samp0, samp1, sb0, sb1, resw);
    quant_lut0<<<(3 * LUT_N + 255) / 256, 256>>>(lut0);
    quant_lut1<<<(3 * LUT_N * 4 + 255) / 256, 256>>>(lut1);

    dim3 blk0(32, 8, 1);
    dim3 grd0(NN / 32, NN / 8, 4);
    stage0_kernel<<<grd0, blk0>>>(x);

    dim3 blk1(32, 8, 1);
    dim3 grd1(NN / 32, NN / 8, 4);
    stage1_kernel<<<grd1, blk1>>>(x, (float*)d_out);
}

// round 14
// speedup vs baseline: 1.1676x; 1.1676x over previous
#include <cuda_runtime.h>
#include <cstdint>

#define NN 512
#define LUT_N 83521            // 17^4
#define NPIX (4 * NN * NN)

// ---------------- device scratch ----------------
__device__ int8_t g_q0[3 * LUT_N];        // stage-0 quantized LUT (int8)
__device__ uint4  g_q1[3 * LUT_N];        // stage-1 quantized LUT (16 ch, biased u8, 16B/row)
__device__ float  g_x1[NPIX];             // stage-0 output image (integers 0..255)

// staging for constant uploads (written by setup_weights, memcpy'd to __constant__)
__device__ unsigned long long g_stg_w0[108];
__device__ unsigned long long g_stg_w1[108];
__device__ unsigned long long g_stg_b0[12];
__device__ unsigned long long g_stg_b1[12];
__device__ float              g_stg_rw[12];

__constant__ unsigned long long c_w0pk[108];  // (w, w) splat pairs, UNfolded (R9 numerics)
__constant__ unsigned long long c_w1pk[108];
__constant__ unsigned long long c_b0pk[12];
__constant__ unsigned long long c_b1pk[12];
__constant__ float              c_rw1[12];

// ---------------- f32x2 helpers ----------------
__device__ __forceinline__ unsigned long long pack2(unsigned lo, unsigned hi) {
    unsigned long long d;
    asm("mov.b64 %0, {%1, %2};" : "=l"(d) : "r"(lo), "r"(hi));
    return d;
}
__device__ __forceinline__ unsigned long long pack2f(float lo, float hi) {
    return pack2(__float_as_uint(lo), __float_as_uint(hi));
}
__device__ __forceinline__ void unpack2(unsigned long long v, float& lo, float& hi) {
    asm("mov.b64 {%0, %1}, %2;" : "=f"(lo), "=f"(hi) : "l"(v));
}
__device__ __forceinline__ unsigned long long swap2(unsigned long long v) {
    float lo, hi; unpack2(v, lo, hi);
    return pack2f(hi, lo);
}
__device__ __forceinline__ unsigned long long fadd2(unsigned long long a, unsigned long long b) {
    unsigned long long d;
    asm("add.rn.f32x2 %0, %1, %2;" : "=l"(d) : "l"(a), "l"(b));
    return d;
}
__device__ __forceinline__ unsigned long long fsub2(unsigned long long a, unsigned long long b) {
    unsigned long long d;
    asm("sub.rn.f32x2 %0, %1, %2;" : "=l"(d) : "l"(a), "l"(b));
    return d;
}
__device__ __forceinline__ unsigned long long ffma2(unsigned long long a, unsigned long long b,
                                                    unsigned long long c) {
    unsigned long long d;
    asm("fma.rn.f32x2 %0, %1, %2, %3;" : "=l"(d) : "l"(a), "l"(b), "l"(c));
    return d;
}
// packed round-to-nearest-even via magic add; 12582912 = 1.5*2^23 = 0x4B400000
// (exact RNE for |x| < 2^22)
#define M2RINT 0x4B4000004B400000ull
__device__ __forceinline__ unsigned long long rint2(unsigned long long a) {
    return fsub2(fadd2(a, M2RINT), M2RINT);
}

// ---------------- setup: splat weights into pairs (values unchanged) ----------------
__global__ void setup_weights(const float* __restrict__ s0, const float* __restrict__ s1,
                              const float* __restrict__ b0, const float* __restrict__ b1,
                              const float* __restrict__ rw) {
    int i = threadIdx.x;
    if (i < 108) {
        g_stg_w0[i] = pack2f(s0[i], s0[i]);
        g_stg_w1[i] = pack2f(s1[i], s1[i]);
    }
    if (i < 12) {
        g_stg_b0[i] = pack2f(b0[i], b0[i]);
        g_stg_b1[i] = pack2f(b1[i], b1[i]);
        g_stg_rw[i] = fminf(fmaxf(rw[i], 0.0f), 1.0f);
    }
}

// ---------------- LUT quantization ----------------
__global__ void quant_lut0(const float* __restrict__ src) {
    int i = blockIdx.x * blockDim.x + threadIdx.x;
    if (i < 3 * LUT_N) {
        float q = rintf(src[i] * 127.0f);
        q = fminf(fmaxf(q, -127.0f), 127.0f);
        g_q0[i] = (int8_t)(int)q;
    }
}

__device__ __forceinline__ unsigned q1_byte(float v) {
    float q = rintf(v * 127.0f);
    q = fminf(fmaxf(q, -127.0f), 127.0f);
    return (unsigned)((int)q + 128);   // biased u8
}

// ---------------- helpers ----------------
// Rotation-r tap position in the 5x5 neighborhood.
// r=0: X[p+u,q+v]; r=1: X[p+v,q-u]; r=2: X[p-u,q-v]; r=3: X[p-v,q+u]
__device__ __forceinline__ constexpr int nb_idx(int R, int u, int w) {
    int dy = (R == 0) ? u : (R == 1) ? w : (R == 2) ? -u : -w;
    int dx = (R == 0) ? w : (R == 1) ? -u : (R == 2) ? -w : u;
    return (2 + dy) * 5 + (2 + dx);
}

#define CSW(fa_, fb_, ta_, tb_)                         \
    { if (fa_ < fb_) { float tf = fa_; fa_ = fb_; fb_ = tf; \
                       int ti = ta_; ta_ = tb_; tb_ = ti; } }

// 4D simplex (R9 numerics); ws pre-scaled by 1/16 (exact)
__device__ __forceinline__ void simplex(const float v[4], int verts[5], float ws[5]) {
    int la = (int)(v[0] * 0.0625f), lb = (int)(v[1] * 0.0625f);
    int lc = (int)(v[2] * 0.0625f), ld = (int)(v[3] * 0.0625f);
    float f0 = v[0] - 16.0f * la, f1 = v[1] - 16.0f * lb;
    float f2 = v[2] - 16.0f * lc, f3 = v[3] - 16.0f * ld;
    int base = la * 4913 + lb * 289 + lc * 17 + ld;
    int t0 = 4913, t1 = 289, t2 = 17, t3 = 1;
    CSW(f0, f1, t0, t1); CSW(f2, f3, t2, t3);
    CSW(f0, f2, t0, t2); CSW(f1, f3, t1, t3);
    CSW(f1, f2, t1, t2);
    ws[0] = (16.0f - f0) * 0.0625f;
    ws[1] = (f0 - f1) * 0.0625f;
    ws[2] = (f1 - f2) * 0.0625f;
    ws[3] = (f2 - f3) * 0.0625f;
    ws[4] = f3 * 0.0625f;
    verts[0] = base;
    verts[1] = verts[0] + t0;
    verts[2] = verts[1] + t1;
    verts[3] = verts[2] + t2;
    verts[4] = verts[3] + t3;
}

// ---------------- merged stage0 + quant_lut1 ----------------
// blockIdx.z == 0: quant1 slice (scheduled first, overlaps stage0 compute).
// blockIdx.z in 1..4: stage0 for batch b = z-1.
__global__ void __launch_bounds__(256, 3) stage0_kernel(const float* __restrict__ x,
                                                        const float* __restrict__ lut1src) {
    if (blockIdx.z == 0) {
        // quant_lut1: word-per-thread, coalesced float4 reads / u32 writes
        int tid = threadIdx.y * 32 + threadIdx.x;
        int gidx = (blockIdx.y * 16 + blockIdx.x) * 256 + tid;   // 262144 threads
        const int W = 3 * LUT_N * 4;
#pragma unroll
        for (int it = 0; it < 4; it++) {
            int i = gidx + it * 262144;
            if (i < W) {
                float4 f = reinterpret_cast<const float4*>(lut1src)[i];
                unsigned acc = q1_byte(f.x) | (q1_byte(f.y) << 8)
                             | (q1_byte(f.z) << 16) | (q1_byte(f.w) << 24);
                reinterpret_cast<unsigned*>(g_q1)[i] = acc;
            }
        }
        return;
    }

    int q = blockIdx.x * 32 + threadIdx.x;
    int p = blockIdx.y * 8 + threadIdx.y;
    int b = blockIdx.z - 1;

    unsigned long long pkA[9], pkB[9];   // (R0,R2) and (R1,R3) packed taps
    {
        const float* img = x + (size_t)b * NN * NN;
        float nb[25];
        int rr[5], cc[5];
#pragma unroll
        for (int i = 0; i < 5; i++) {
            rr[i] = min(max(p - 2 + i, 0), NN - 1);
            cc[i] = min(max(q - 2 + i, 0), NN - 1);
        }
#pragma unroll
        for (int i = 0; i < 5; i++)
#pragma unroll
            for (int j = 0; j < 5; j++)
                nb[i * 5 + j] = 255.0f * __ldg(img + rr[i] * NN + cc[j]);
#pragma unroll
        for (int u = 0; u < 3; u++)
#pragma unroll
            for (int w = 0; w < 3; w++) {
                int iA = nb_idx(0, u, w);
                int iB = nb_idx(1, u, w);
                pkA[u * 3 + w] = pack2f(nb[iA], nb[24 - iA]);
                pkB[u * 3 + w] = pack2f(nb[iB], nb[24 - iB]);
            }
    }

    float total = 0.0f;
#pragma unroll
    for (int s = 0; s < 3; s++) {
        const int8_t* lt = g_q0 + s * LUT_N;

        float v[4][4];
#pragma unroll
        for (int ch = 0; ch < 4; ch++) {
            unsigned long long accA = c_b0pk[s * 4 + ch];
            unsigned long long accB = accA;
#pragma unroll
            for (int t = 0; t < 9; t++) {
                unsigned long long w2 = c_w0pk[s * 36 + ch * 9 + t];
                accA = ffma2(w2, pkA[t], accA);
                accB = ffma2(w2, pkB[t], accB);
            }
            unpack2(accA, v[0][ch], v[2][ch]);
            unpack2(accB, v[1][ch], v[3][ch]);
        }

        float acc = 0.0f;
#pragma unroll
        for (int R = 0; R < 4; R++) {
            int verts[5]; float ws[5];
            simplex(v[R], verts, ws);
            float dot = 0.0f;
#pragma unroll
            for (int t = 0; t < 5; t++) dot += ws[t] * (float)__ldg(lt + verts[t]);
            acc = rintf(acc + dot);
        }
        total += acc;
    }
    float o = rintf(fminf(fmaxf(total * (1.0f / 12.0f) + 127.0f, 0.0f), 255.0f));
    g_x1[(size_t)b * NN * NN + p * NN + q] = o;
}

// ---------------- stage 1 ----------------
// fused per-rotation: simplex + gather + accumulate into packed blk2[8] (pairs of channels);
// blk2 += rint2(c)  — exact RNE, integer-valued accumulators, order-free
template <int R>
__device__ __forceinline__ void proc_rot1(const float v[4], const uint4* __restrict__ lt,
                                          unsigned long long blk2[8]) {
    int vt[5]; float ws[5];
    simplex(v, vt, ws);

    uint4 d[5];
#pragma unroll
    for (int t = 0; t < 5; t++) d[t] = __ldg(lt + vt[t]);

    unsigned long long c2[8];
#pragma unroll
    for (int pidx = 0; pidx < 8; pidx++) c2[pidx] = 0ull;
    const unsigned long long B2 = pack2(0xCB000080u, 0xCB000080u);  // (-8388736,-8388736)

#pragma unroll
    for (int t = 0; t < 5; t++) {
        unsigned wtb = __float_as_uint(ws[t]);
        unsigned long long wt2 = pack2(wtb, wtb);
#pragma unroll
        for (int pidx = 0; pidx < 8; pidx++) {
            unsigned word = (pidx < 2) ? d[t].x : (pidx < 4) ? d[t].y
                          : (pidx < 6) ? d[t].z : d[t].w;
            int kk = (pidx & 1) * 2;
            unsigned lo = __byte_perm(word, 0x4B000000u, 0x7540u + kk);
            unsigned hi = __byte_perm(word, 0x4B000000u, 0x7541u + kk);
            unsigned long long m2 = fadd2(pack2(lo, hi), B2);  // exact (byte-128)
            c2[pidx] = ffma2(m2, wt2, c2[pidx]);
        }
    }

    if (R == 0) {
        // identity: blk pair b <- c pair b
#pragma unroll
        for (int bq = 0; bq < 8; bq++)
            blk2[bq] = fadd2(blk2[bq], rint2(c2[bq]));
    } else if (R == 2) {
        // k = 15 - (i*4+j): blk pair b <- c pair 7-b, lanes swapped
#pragma unroll
        for (int bq = 0; bq < 8; bq++)
            blk2[bq] = fadd2(blk2[bq], swap2(rint2(c2[7 - bq])));
    } else {
        float c[16];
#pragma unroll
        for (int pidx = 0; pidx < 8; pidx++) unpack2(c2[pidx], c[2 * pidx], c[2 * pidx + 1]);
#pragma unroll
        for (int bq = 0; bq < 8; bq++) {
            int i = bq >> 1, j0 = (bq & 1) * 2;
            int k0 = (R == 1) ? ((3 - j0) * 4 + i) : (j0 * 4 + (3 - i));
            int k1 = (R == 1) ? ((3 - j0 - 1) * 4 + i) : ((j0 + 1) * 4 + (3 - i));
            blk2[bq] = fadd2(blk2[bq], rint2(pack2f(c[k0], c[k1])));
        }
    }
}

__global__ void __launch_bounds__(256, 2) stage1_kernel(const float* __restrict__ x,
                                                        float* __restrict__ out) {
    int q = blockIdx.x * 32 + threadIdx.x;
    int p = blockIdx.y * 8 + threadIdx.y;
    int b = blockIdx.z;

    // packed neighborhood: lane0 = current image (g_x1), lane1 = prev image (255*x)
    unsigned long long pnb[25];
    {
        const float* img1 = g_x1 + (size_t)b * NN * NN;
        const float* img0 = x + (size_t)b * NN * NN;
        int rr[5], cc[5];
#pragma unroll
        for (int i = 0; i < 5; i++) {
            rr[i] = min(max(p - 2 + i, 0), NN - 1);
            cc[i] = min(max(q - 2 + i, 0), NN - 1);
        }
#pragma unroll
        for (int i = 0; i < 5; i++)
#pragma unroll
            for (int j = 0; j < 5; j++) {
                int off = rr[i] * NN + cc[j];
                pnb[i * 5 + j] = pack2f(__ldg(img1 + off), 255.0f * __ldg(img0 + off));
            }
    }

    unsigned long long blk2[8];
#pragma unroll
    for (int k = 0; k < 8; k++) blk2[k] = 0ull;

#pragma unroll
    for (int s = 0; s < 3; s++) {
        const uint4* lt = g_q1 + s * LUT_N;

        // ---- paired conv (cur, prev share weights), splatted constant pairs ----
        float v[4][4];   // [R][ch], blended
#pragma unroll
        for (int ch = 0; ch < 4; ch++) {
            unsigned long long B2b = c_b1pk[s * 4 + ch];
            float rwc = c_rw1[s * 4 + ch];
#pragma unroll
            for (int R = 0; R < 4; R++) {
                unsigned long long a2 = B2b;
#pragma unroll
                for (int u = 0; u < 3; u++)
#pragma unroll
                    for (int w = 0; w < 3; w++)
                        a2 = ffma2(c_w1pk[s * 36 + ch * 9 + u * 3 + w],
                                   pnb[nb_idx(R, u, w)], a2);
                float vc, vp;
                unpack2(a2, vc, vp);
                v[R][ch] = vc + rwc * (vp - vc);
            }
        }

        proc_rot1<0>(v[0], lt, blk2);
        proc_rot1<1>(v[1], lt, blk2);
        proc_rot1<2>(v[2], lt, blk2);
        proc_rot1<3>(v[3], lt, blk2);
    }

    float blk[16];
#pragma unroll
    for (int k = 0; k < 8; k++) unpack2(blk2[k], blk[2 * k], blk[2 * k + 1]);

    float* op = out + ((size_t)b << 22) + (size_t)(4 * p) * 2048 + 4 * q;
#pragma unroll
    for (int i = 0; i < 4; i++) {
        float4 o;
        o.x = rintf(fminf(fmaxf(blk[i * 4 + 0] * (1.0f / 3.0f), 0.0f), 255.0f)) * (1.0f / 255.0f);
        o.y = rintf(fminf(fmaxf(blk[i * 4 + 1] * (1.0f / 3.0f), 0.0f), 255.0f)) * (1.0f / 255.0f);
        o.z = rintf(fminf(fmaxf(blk[i * 4 + 2] * (1.0f / 3.0f), 0.0f), 255.0f)) * (1.0f / 255.0f);
        o.w = rintf(fminf(fmaxf(blk[i * 4 + 3] * (1.0f / 3.0f), 0.0f), 255.0f)) * (1.0f / 255.0f);
        *reinterpret_cast<float4*>(op + (size_t)i * 2048) = o;
    }
}

// ---------------- launch ----------------
extern "C" void kernel_launch(void* const* d_in, const int* in_sizes, int n_in,
                              void* d_out, int out_size) {
    const float* x     = (const float*)d_in[0];
    const float* lut0  = (const float*)d_in[1];
    const float* lut1  = (const float*)d_in[2];
    const float* samp0 = (const float*)d_in[3];
    const float* samp1 = (const float*)d_in[4];
    const float* sb0   = (const float*)d_in[5];
    const float* sb1   = (const float*)d_in[6];
    const float* resw  = (const float*)d_in[7];

    setup_weights<<<1, 128>>>(samp0, samp1, sb0, sb1, resw);

    void *pw0, *pw1, *pb0, *pb1, *prw;
    cudaGetSymbolAddress(&pw0, g_stg_w0);
    cudaGetSymbolAddress(&pw1, g_stg_w1);
    cudaGetSymbolAddress(&pb0, g_stg_b0);
    cudaGetSymbolAddress(&pb1, g_stg_b1);
    cudaGetSymbolAddress(&prw, g_stg_rw);
    cudaMemcpyToSymbolAsync(c_w0pk, pw0, 108 * 8, 0, cudaMemcpyDeviceToDevice);
    cudaMemcpyToSymbolAsync(c_w1pk, pw1, 108 * 8, 0, cudaMemcpyDeviceToDevice);
    cudaMemcpyToSymbolAsync(c_b0pk, pb0, 12 * 8, 0, cudaMemcpyDeviceToDevice);
    cudaMemcpyToSymbolAsync(c_b1pk, pb1, 12 * 8, 0, cudaMemcpyDeviceToDevice);
    cudaMemcpyToSymbolAsync(c_rw1,  prw, 12 * 4, 0, cudaMemcpyDeviceToDevice);

    quant_lut0<<<(3 * LUT_N + 255) / 256, 256>>>(lut0);

    dim3 blk0(32, 8, 1);
    dim3 grd0(NN / 32, NN / 8, 5);   // z=0: quant1 slice; z=1..4: stage0 batches
    stage0_kernel<<<grd0, blk0>>>(x, lut1);

    dim3 blk1(32, 8, 1);
    dim3 grd1(NN / 32, NN / 8, 4);
    stage1_kernel<<<grd1, blk1>>>(x, (float*)d_out);
}

// round 15
// speedup vs baseline: 1.1990x; 1.0269x over previous
#include <cuda_runtime.h>
#include <cstdint>

#define NN 512
#define LUT_N 83521            // 17^4
#define NPIX (4 * NN * NN)

// ---------------- device scratch ----------------
__device__ int8_t g_q0[3 * LUT_N];        // stage-0 quantized LUT (int8)
__device__ uint4  g_q1[3 * LUT_N];        // stage-1 quantized LUT (16 ch, biased u8, 16B/row)
__device__ float  g_x1[NPIX];             // stage-0 output image (integers 0..255)

// staging for constant uploads (written by setup_weights, memcpy'd to __constant__)
__device__ unsigned long long g_stg_w0[108];
__device__ unsigned long long g_stg_w1[108];
__device__ unsigned long long g_stg_b0[12];
__device__ unsigned long long g_stg_b1[12];
__device__ float              g_stg_rw[12];

__constant__ unsigned long long c_w0pk[108];  // (w, w) splat pairs (R9 numerics)
__constant__ unsigned long long c_w1pk[108];
__constant__ unsigned long long c_b0pk[12];
__constant__ unsigned long long c_b1pk[12];
__constant__ float              c_rw1[12];

// ---------------- f32x2 helpers ----------------
__device__ __forceinline__ unsigned long long pack2(unsigned lo, unsigned hi) {
    unsigned long long d;
    asm("mov.b64 %0, {%1, %2};" : "=l"(d) : "r"(lo), "r"(hi));
    return d;
}
__device__ __forceinline__ unsigned long long pack2f(float lo, float hi) {
    return pack2(__float_as_uint(lo), __float_as_uint(hi));
}
__device__ __forceinline__ void unpack2(unsigned long long v, float& lo, float& hi) {
    asm("mov.b64 {%0, %1}, %2;" : "=f"(lo), "=f"(hi) : "l"(v));
}
__device__ __forceinline__ unsigned long long swap2(unsigned long long v) {
    float lo, hi; unpack2(v, lo, hi);
    return pack2f(hi, lo);
}
__device__ __forceinline__ unsigned long long fadd2(unsigned long long a, unsigned long long b) {
    unsigned long long d;
    asm("add.rn.f32x2 %0, %1, %2;" : "=l"(d) : "l"(a), "l"(b));
    return d;
}
__device__ __forceinline__ unsigned long long ffma2(unsigned long long a, unsigned long long b,
                                                    unsigned long long c) {
    unsigned long long d;
    asm("fma.rn.f32x2 %0, %1, %2, %3;" : "=l"(d) : "l"(a), "l"(b), "l"(c));
    return d;
}
// magic offset: 12582912 = 1.5*2^23 = 0x4B400000. Accumulators kept at M+value
// stay in [2^23, 2^24) where ulp = 1, so every fadd IS a round-to-nearest-int.
#define MAGIC_F 12582912.0f
#define M2RINT 0x4B4000004B400000ull

// ---------------- setup: splat weights into pairs (values unchanged) ----------------
__global__ void setup_weights(const float* __restrict__ s0, const float* __restrict__ s1,
                              const float* __restrict__ b0, const float* __restrict__ b1,
                              const float* __restrict__ rw) {
    int i = threadIdx.x;
    if (i < 108) {
        g_stg_w0[i] = pack2f(s0[i], s0[i]);
        g_stg_w1[i] = pack2f(s1[i], s1[i]);
    }
    if (i < 12) {
        g_stg_b0[i] = pack2f(b0[i], b0[i]);
        g_stg_b1[i] = pack2f(b1[i], b1[i]);
        g_stg_rw[i] = fminf(fmaxf(rw[i], 0.0f), 1.0f);
    }
}

// ---------------- LUT quantization ----------------
__global__ void quant_lut0(const float* __restrict__ src) {
    int i = blockIdx.x * blockDim.x + threadIdx.x;
    if (i < 3 * LUT_N) {
        float q = rintf(src[i] * 127.0f);
        q = fminf(fmaxf(q, -127.0f), 127.0f);
        g_q0[i] = (int8_t)(int)q;
    }
}

__device__ __forceinline__ unsigned q1_byte(float v) {
    float q = rintf(v * 127.0f);
    q = fminf(fmaxf(q, -127.0f), 127.0f);
    return (unsigned)((int)q + 128);   // biased u8
}

// ---------------- helpers ----------------
// Rotation-r tap position in the 5x5 neighborhood.
// r=0: X[p+u,q+v]; r=1: X[p+v,q-u]; r=2: X[p-u,q-v]; r=3: X[p-v,q+u]
__device__ __forceinline__ constexpr int nb_idx(int R, int u, int w) {
    int dy = (R == 0) ? u : (R == 1) ? w : (R == 2) ? -u : -w;
    int dx = (R == 0) ? w : (R == 1) ? -u : (R == 2) ? -w : u;
    return (2 + dy) * 5 + (2 + dx);
}

#define CSW(fa_, fb_, ta_, tb_)                         \
    { if (fa_ < fb_) { float tf = fa_; fa_ = fb_; fb_ = tf; \
                       int ti = ta_; ta_ = tb_; tb_ = ti; } }

// 4D simplex, scaled form: t = v/16 (exact), f' = frac(t); ws need no /16
// (bit-identical to R9: each ws rounds at the same relative position, scale exact)
__device__ __forceinline__ void simplex(const float v[4], int verts[5], float ws[5]) {
    float ta = v[0] * 0.0625f, tb = v[1] * 0.0625f;
    float tc = v[2] * 0.0625f, td = v[3] * 0.0625f;
    int la = (int)ta, lb = (int)tb, lc = (int)tc, ld = (int)td;
    float f0 = ta - (float)la, f1 = tb - (float)lb;
    float f2 = tc - (float)lc, f3 = td - (float)ld;
    int base = la * 4913 + lb * 289 + lc * 17 + ld;
    int t0 = 4913, t1 = 289, t2 = 17, t3 = 1;
    CSW(f0, f1, t0, t1); CSW(f2, f3, t2, t3);
    CSW(f0, f2, t0, t2); CSW(f1, f3, t1, t3);
    CSW(f1, f2, t1, t2);
    ws[0] = 1.0f - f0;
    ws[1] = f0 - f1;
    ws[2] = f1 - f2;
    ws[3] = f2 - f3;
    ws[4] = f3;
    verts[0] = base;
    verts[1] = verts[0] + t0;
    verts[2] = verts[1] + t1;
    verts[3] = verts[2] + t2;
    verts[4] = verts[3] + t3;
}

// ---------------- merged stage0 + quant_lut1 ----------------
// blockIdx.z == 0: quant1 slice (scheduled first, overlaps stage0 compute).
// blockIdx.z in 1..4: stage0 for batch b = z-1.
__global__ void __launch_bounds__(256, 3) stage0_kernel(const float* __restrict__ x,
                                                        const float* __restrict__ lut1src) {
    if (blockIdx.z == 0) {
        int tid = threadIdx.y * 32 + threadIdx.x;
        int gidx = (blockIdx.y * 16 + blockIdx.x) * 256 + tid;   // 262144 threads
        const int W = 3 * LUT_N * 4;
#pragma unroll
        for (int it = 0; it < 4; it++) {
            int i = gidx + it * 262144;
            if (i < W) {
                float4 f = reinterpret_cast<const float4*>(lut1src)[i];
                unsigned acc = q1_byte(f.x) | (q1_byte(f.y) << 8)
                             | (q1_byte(f.z) << 16) | (q1_byte(f.w) << 24);
                reinterpret_cast<unsigned*>(g_q1)[i] = acc;
            }
        }
        return;
    }

    int q = blockIdx.x * 32 + threadIdx.x;
    int p = blockIdx.y * 8 + threadIdx.y;
    int b = blockIdx.z - 1;

    unsigned long long pkA[9], pkB[9];   // (R0,R2) and (R1,R3) packed taps
    {
        const float* img = x + (size_t)b * NN * NN;
        float nb[25];
        int rr[5], cc[5];
#pragma unroll
        for (int i = 0; i < 5; i++) {
            rr[i] = min(max(p - 2 + i, 0), NN - 1);
            cc[i] = min(max(q - 2 + i, 0), NN - 1);
        }
#pragma unroll
        for (int i = 0; i < 5; i++)
#pragma unroll
            for (int j = 0; j < 5; j++)
                nb[i * 5 + j] = 255.0f * __ldg(img + rr[i] * NN + cc[j]);
#pragma unroll
        for (int u = 0; u < 3; u++)
#pragma unroll
            for (int w = 0; w < 3; w++) {
                int iA = nb_idx(0, u, w);
                int iB = nb_idx(1, u, w);
                pkA[u * 3 + w] = pack2f(nb[iA], nb[24 - iA]);
                pkB[u * 3 + w] = pack2f(nb[iB], nb[24 - iB]);
            }
    }

    // magic-domain rintf chain: total_m += dot rounds (total + dot) to int (ulp=1)
    float total_m = MAGIC_F;
#pragma unroll
    for (int s = 0; s < 3; s++) {
        const int8_t* lt = g_q0 + s * LUT_N;

        float v[4][4];
#pragma unroll
        for (int ch = 0; ch < 4; ch++) {
            unsigned long long accA = c_b0pk[s * 4 + ch];
            unsigned long long accB = accA;
#pragma unroll
            for (int t = 0; t < 9; t++) {
                unsigned long long w2 = c_w0pk[s * 36 + ch * 9 + t];
                accA = ffma2(w2, pkA[t], accA);
                accB = ffma2(w2, pkB[t], accB);
            }
            unpack2(accA, v[0][ch], v[2][ch]);
            unpack2(accB, v[1][ch], v[3][ch]);
        }

#pragma unroll
        for (int R = 0; R < 4; R++) {
            int verts[5]; float ws[5];
            simplex(v[R], verts, ws);
            float dot = 0.0f;
#pragma unroll
            for (int t = 0; t < 5; t++) dot += ws[t] * (float)__ldg(lt + verts[t]);
            total_m += dot;   // auto-rint at ulp 1
        }
    }
    float total = total_m - MAGIC_F;
    float o = rintf(fminf(fmaxf(total * (1.0f / 12.0f) + 127.0f, 0.0f), 255.0f));
    g_x1[(size_t)b * NN * NN + p * NN + q] = o;
}

// ---------------- stage 1 ----------------
// fused per-rotation: simplex + gather + accumulate into magic-domain blk2[8];
// blk2 += c2 rounds (blk + c) to nearest int per lane (ulp=1) == blk += rint(c)
template <int R>
__device__ __forceinline__ void proc_rot1(const float v[4], const uint4* __restrict__ lt,
                                          unsigned long long blk2[8]) {
    int vt[5]; float ws[5];
    simplex(v, vt, ws);

    uint4 d[5];
#pragma unroll
    for (int t = 0; t < 5; t++) d[t] = __ldg(lt + vt[t]);

    unsigned long long c2[8];
#pragma unroll
    for (int pidx = 0; pidx < 8; pidx++) c2[pidx] = 0ull;
    const unsigned long long B2 = pack2(0xCB000080u, 0xCB000080u);  // (-8388736,-8388736)

#pragma unroll
    for (int t = 0; t < 5; t++) {
        unsigned wtb = __float_as_uint(ws[t]);
        unsigned long long wt2 = pack2(wtb, wtb);
#pragma unroll
        for (int pidx = 0; pidx < 8; pidx++) {
            unsigned word = (pidx < 2) ? d[t].x : (pidx < 4) ? d[t].y
                          : (pidx < 6) ? d[t].z : d[t].w;
            int kk = (pidx & 1) * 2;
            unsigned lo = __byte_perm(word, 0x4B000000u, 0x7540u + kk);
            unsigned hi = __byte_perm(word, 0x4B000000u, 0x7541u + kk);
            unsigned long long m2 = fadd2(pack2(lo, hi), B2);  // exact (byte-128)
            c2[pidx] = ffma2(m2, wt2, c2[pidx]);
        }
    }

    if (R == 0) {
#pragma unroll
        for (int bq = 0; bq < 8; bq++)
            blk2[bq] = fadd2(blk2[bq], c2[bq]);
    } else if (R == 2) {
        // k = 15 - (i*4+j): blk pair b <- c pair 7-b, lanes swapped
#pragma unroll
        for (int bq = 0; bq < 8; bq++)
            blk2[bq] = fadd2(blk2[bq], swap2(c2[7 - bq]));
    } else {
        float c[16];
#pragma unroll
        for (int pidx = 0; pidx < 8; pidx++) unpack2(c2[pidx], c[2 * pidx], c[2 * pidx + 1]);
#pragma unroll
        for (int bq = 0; bq < 8; bq++) {
            int i = bq >> 1, j0 = (bq & 1) * 2;
            int k0 = (R == 1) ? ((3 - j0) * 4 + i) : (j0 * 4 + (3 - i));
            int k1 = (R == 1) ? ((3 - j0 - 1) * 4 + i) : ((j0 + 1) * 4 + (3 - i));
            blk2[bq] = fadd2(blk2[bq], pack2f(c[k0], c[k1]));
        }
    }
}

__global__ void __launch_bounds__(256, 2) stage1_kernel(const float* __restrict__ x,
                                                        float* __restrict__ out) {
    int q = blockIdx.x * 32 + threadIdx.x;
    int p = blockIdx.y * 8 + threadIdx.y;
    int b = blockIdx.z;

    // packed neighborhood: lane0 = current image (g_x1), lane1 = prev image (255*x)
    unsigned long long pnb[25];
    {
        const float* img1 = g_x1 + (size_t)b * NN * NN;
        const float* img0 = x + (size_t)b * NN * NN;
        int rr[5], cc[5];
#pragma unroll
        for (int i = 0; i < 5; i++) {
            rr[i] = min(max(p - 2 + i, 0), NN - 1);
            cc[i] = min(max(q - 2 + i, 0), NN - 1);
        }
#pragma unroll
        for (int i = 0; i < 5; i++)
#pragma unroll
            for (int j = 0; j < 5; j++) {
                int off = rr[i] * NN + cc[j];
                pnb[i * 5 + j] = pack2f(__ldg(img1 + off), 255.0f * __ldg(img0 + off));
            }
    }

    unsigned long long blk2[8];
#pragma unroll
    for (int k = 0; k < 8; k++) blk2[k] = M2RINT;   // magic-domain zero

#pragma unroll
    for (int s = 0; s < 3; s++) {
        const uint4* lt = g_q1 + s * LUT_N;

        // ---- paired conv (cur, prev share weights), splatted constant pairs ----
        float v[4][4];   // [R][ch], blended
#pragma unroll
        for (int ch = 0; ch < 4; ch++) {
            unsigned long long B2b = c_b1pk[s * 4 + ch];
            float rwc = c_rw1[s * 4 + ch];
#pragma unroll
            for (int R = 0; R < 4; R++) {
                unsigned long long a2 = B2b;
#pragma unroll
                for (int u = 0; u < 3; u++)
#pragma unroll
                    for (int w = 0; w < 3; w++)
                        a2 = ffma2(c_w1pk[s * 36 + ch * 9 + u * 3 + w],
                                   pnb[nb_idx(R, u, w)], a2);
                float vc, vp;
                unpack2(a2, vc, vp);
                v[R][ch] = vc + rwc * (vp - vc);
            }
        }

        proc_rot1<0>(v[0], lt, blk2);
        proc_rot1<1>(v[1], lt, blk2);
        proc_rot1<2>(v[2], lt, blk2);
        proc_rot1<3>(v[3], lt, blk2);
    }

    float blk[16];
#pragma unroll
    for (int k = 0; k < 8; k++) {
        float lo, hi;
        unpack2(blk2[k], lo, hi);
        blk[2 * k] = lo - MAGIC_F;       // exact
        blk[2 * k + 1] = hi - MAGIC_F;
    }

    float* op = out + ((size_t)b << 22) + (size_t)(4 * p) * 2048 + 4 * q;
#pragma unroll
    for (int i = 0; i < 4; i++) {
        float4 o;
        o.x = rintf(fminf(fmaxf(blk[i * 4 + 0] * (1.0f / 3.0f), 0.0f), 255.0f)) * (1.0f / 255.0f);
        o.y = rintf(fminf(fmaxf(blk[i * 4 + 1] * (1.0f / 3.0f), 0.0f), 255.0f)) * (1.0f / 255.0f);
        o.z = rintf(fminf(fmaxf(blk[i * 4 + 2] * (1.0f / 3.0f), 0.0f), 255.0f)) * (1.0f / 255.0f);
        o.w = rintf(fminf(fmaxf(blk[i * 4 + 3] * (1.0f / 3.0f), 0.0f), 255.0f)) * (1.0f / 255.0f);
        *reinterpret_cast<float4*>(op + (size_t)i * 2048) = o;
    }
}

// ---------------- launch ----------------
extern "C" void kernel_launch(void* const* d_in, const int* in_sizes, int n_in,
                              void* d_out, int out_size) {
    const float* x     = (const float*)d_in[0];
    const float* lut0  = (const float*)d_in[1];
    const float* lut1  = (const float*)d_in[2];
    const float* samp0 = (const float*)d_in[3];
    const float* samp1 = (const float*)d_in[4];
    const float* sb0   = (const float*)d_in[5];
    const float* sb1   = (const float*)d_in[6];
    const float* resw  = (const float*)d_in[7];

    setup_weights<<<1, 128>>>(samp0, samp1, sb0, sb1, resw);

    void *pw0, *pw1, *pb0, *pb1, *prw;
    cudaGetSymbolAddress(&pw0, g_stg_w0);
    cudaGetSymbolAddress(&pw1, g_stg_w1);
    cudaGetSymbolAddress(&pb0, g_stg_b0);
    cudaGetSymbolAddress(&pb1, g_stg_b1);
    cudaGetSymbolAddress(&prw, g_stg_rw);
    cudaMemcpyToSymbolAsync(c_w0pk, pw0, 108 * 8, 0, cudaMemcpyDeviceToDevice);
    cudaMemcpyToSymbolAsync(c_w1pk, pw1, 108 * 8, 0, cudaMemcpyDeviceToDevice);
    cudaMemcpyToSymbolAsync(c_b0pk, pb0, 12 * 8, 0, cudaMemcpyDeviceToDevice);
    cudaMemcpyToSymbolAsync(c_b1pk, pb1, 12 * 8, 0, cudaMemcpyDeviceToDevice);
    cudaMemcpyToSymbolAsync(c_rw1,  prw, 12 * 4, 0, cudaMemcpyDeviceToDevice);

    quant_lut0<<<(3 * LUT_N + 255) / 256, 256>>>(lut0);

    dim3 blk0(32, 8, 1);
    dim3 grd0(NN / 32, NN / 8, 5);   // z=0: quant1 slice; z=1..4: stage0 batches
    stage0_kernel<<<grd0, blk0>>>(x, lut1);

    dim3 blk1(32, 8, 1);
    dim3 grd1(NN / 32, NN / 8, 4);
    stage1_kernel<<<grd1, blk1>>>(x, (float*)d_out);
}